// round 1
// baseline (speedup 1.0000x reference)
#include <cuda_runtime.h>

#define N_NODES 50000
#define N_EDGES 800000
#define E_TOT   850000      // edges + self loops
#define F0      128         // input channels
#define F1      128         // layer1 width = H1*C1
#define H1      4
#define C1      32
#define F2      64          // layer2 out channels (H=1)
#define NEG     0.2f
#define EPS_Z   1e-16f

// ---------------- scratch (static device allocations) ----------------
__device__ float g_h1[N_NODES * F1];
__device__ float g_as1[N_NODES * H1];
__device__ float g_ad1[N_NODES * H1];
__device__ int   g_m1[N_NODES * H1];
__device__ float g_z1[N_NODES * H1];
__device__ float g_alpha1[(long)E_TOT * H1];
__device__ float g_agg1[N_NODES * F1];
__device__ float g_h2[N_NODES * F2];
__device__ float g_as2[N_NODES];
__device__ float g_ad2[N_NODES];
__device__ int   g_m2[N_NODES];
__device__ float g_z2[N_NODES];
__device__ float g_alpha2[E_TOT];

// order-preserving int encoding for float atomicMax
__device__ __forceinline__ int enc_f(float f) {
    int i = __float_as_int(f);
    return (i >= 0) ? i : (i ^ 0x7fffffff);
}
__device__ __forceinline__ float dec_f(int e) {
    int i = (e >= 0) ? e : (e ^ 0x7fffffff);
    return __int_as_float(i);
}

__device__ __forceinline__ void edge_sd(const int* __restrict__ ei, int e, int& s, int& d) {
    if (e < N_EDGES) { s = ei[e]; d = ei[N_EDGES + e]; }
    else             { s = e - N_EDGES; d = s; }
}

// ---------------- init ----------------
__global__ void init_kernel(float* __restrict__ out) {
    int i = blockIdx.x * blockDim.x + threadIdx.x;
    if (i < N_NODES * F1) g_agg1[i] = 0.f;
    if (i < N_NODES * F2) out[i] = 0.f;
    if (i < N_NODES * H1) { g_z1[i] = 0.f; g_m1[i] = INT_MIN; }
    if (i < N_NODES)      { g_z2[i] = 0.f; g_m2[i] = INT_MIN; }
}

// ---------------- layer1 GEMM + attention dots ----------------
// blockDim = 128 (thread j = output channel). 16 nodes per block, 4 at a time.
__global__ __launch_bounds__(128) void gemm1_kernel(
    const float* __restrict__ x, const float* __restrict__ W,
    const float* __restrict__ attS, const float* __restrict__ attD)
{
    __shared__ float xs[4][F0];
    __shared__ float sAs[F1], sAd[F1];
    const int j = threadIdx.x;
    sAs[j] = attS[j];
    sAd[j] = attD[j];
    const int head = j >> 5;
    const int base = blockIdx.x * 16;

    for (int g0 = 0; g0 < 16; g0 += 4) {
        __syncthreads();
        #pragma unroll
        for (int r = 0; r < 4; r++) {
            int n = base + g0 + r;
            xs[r][j] = (n < N_NODES) ? x[n * F0 + j] : 0.f;
        }
        __syncthreads();

        float acc0 = 0.f, acc1 = 0.f, acc2 = 0.f, acc3 = 0.f;
        #pragma unroll 8
        for (int k = 0; k < F0; k++) {
            float w = W[k * F1 + j];     // coalesced, L1/L2 resident
            acc0 = fmaf(w, xs[0][k], acc0);
            acc1 = fmaf(w, xs[1][k], acc1);
            acc2 = fmaf(w, xs[2][k], acc2);
            acc3 = fmaf(w, xs[3][k], acc3);
        }

        float accs[4] = {acc0, acc1, acc2, acc3};
        #pragma unroll
        for (int r = 0; r < 4; r++) {
            int n = base + g0 + r;
            if (n >= N_NODES) break;
            float v = accs[r];
            g_h1[n * F1 + j] = v;
            float ps = v * sAs[j];
            float pd = v * sAd[j];
            #pragma unroll
            for (int off = 16; off > 0; off >>= 1) {
                ps += __shfl_down_sync(0xffffffffu, ps, off);
                pd += __shfl_down_sync(0xffffffffu, pd, off);
            }
            if ((j & 31) == 0) {
                g_as1[n * H1 + head] = ps;
                g_ad1[n * H1 + head] = pd;
            }
        }
    }
}

// ---------------- layer2 GEMM (input = relu(agg1 + b1)) ----------------
// blockDim = 64 (thread j = output channel). 8 nodes per block.
__global__ __launch_bounds__(64) void gemm2_kernel(
    const float* __restrict__ b1, const float* __restrict__ W,
    const float* __restrict__ attS, const float* __restrict__ attD)
{
    __shared__ float xs[F1];
    __shared__ float red[4];
    const int j = threadIdx.x;   // 0..63
    const int warp = j >> 5;
    const int base = blockIdx.x * 8;

    for (int g = 0; g < 8; g++) {
        int n = base + g;
        if (n >= N_NODES) return;
        __syncthreads();
        // load relu(agg1 + b1) row: 128 floats by 64 threads
        xs[j]      = fmaxf(g_agg1[n * F1 + j]      + b1[j],      0.f);
        xs[j + 64] = fmaxf(g_agg1[n * F1 + j + 64] + b1[j + 64], 0.f);
        __syncthreads();

        float acc = 0.f;
        #pragma unroll 8
        for (int k = 0; k < F1; k++)
            acc = fmaf(W[k * F2 + j], xs[k], acc);

        g_h2[n * F2 + j] = acc;
        float ps = acc * attS[j];
        float pd = acc * attD[j];
        #pragma unroll
        for (int off = 16; off > 0; off >>= 1) {
            ps += __shfl_down_sync(0xffffffffu, ps, off);
            pd += __shfl_down_sync(0xffffffffu, pd, off);
        }
        if ((j & 31) == 0) { red[warp] = ps; red[2 + warp] = pd; }
        __syncthreads();
        if (j == 0) {
            g_as2[n] = red[0] + red[1];
            g_ad2[n] = red[2] + red[3];
        }
    }
}

// ---------------- edge pass A: alpha + segment max ----------------
template<int H>
__global__ void edge_max_kernel(const int* __restrict__ ei,
                                const float* __restrict__ as_,
                                const float* __restrict__ ad_,
                                float* __restrict__ alpha,
                                int* __restrict__ m)
{
    int idx = blockIdx.x * blockDim.x + threadIdx.x;
    if (idx >= E_TOT * H) return;
    int e = idx / H, h = idx % H;
    int s, d;
    edge_sd(ei, e, s, d);
    float a = as_[s * H + h] + ad_[d * H + h];
    a = (a > 0.f) ? a : NEG * a;
    alpha[idx] = a;
    atomicMax(&m[d * H + h], enc_f(a));
}

// ---------------- edge pass B: exp + segment sum ----------------
template<int H>
__global__ void edge_sum_kernel(const int* __restrict__ ei,
                                const int* __restrict__ m,
                                float* __restrict__ alpha,
                                float* __restrict__ z)
{
    int idx = blockIdx.x * blockDim.x + threadIdx.x;
    if (idx >= E_TOT * H) return;
    int e = idx / H, h = idx % H;
    int s, d;
    edge_sd(ei, e, s, d);
    float mv = dec_f(m[d * H + h]);
    float ev = expf(alpha[idx] - mv);
    alpha[idx] = ev;
    atomicAdd(&z[d * H + h], ev);
}

// ---------------- edge pass C: normalize + aggregate ----------------
// One thread per (edge, float4-quad). QPE = H*C/4 quads per edge.
template<int H, int C>
__global__ void edge_agg_kernel(const int* __restrict__ ei,
                                const float* __restrict__ hfeat,
                                const float* __restrict__ alpha,
                                const float* __restrict__ z,
                                float* __restrict__ agg)
{
    const int QPE = H * C / 4;
    int idx = blockIdx.x * blockDim.x + threadIdx.x;
    if (idx >= E_TOT * QPE) return;
    int e = idx / QPE;
    int q = idx % QPE;
    int f = q * 4;
    int h = f / C;
    int s, d;
    edge_sd(ei, e, s, d);
    float coef = alpha[e * H + h] / (z[d * H + h] + EPS_Z);
    float4 v = *reinterpret_cast<const float4*>(&hfeat[(long)s * (H * C) + f]);
    float4 r;
    r.x = v.x * coef; r.y = v.y * coef; r.z = v.z * coef; r.w = v.w * coef;
    float* dst = &agg[(long)d * (H * C) + f];
    asm volatile("red.global.add.v4.f32 [%0], {%1,%2,%3,%4};"
                 :: "l"(dst), "f"(r.x), "f"(r.y), "f"(r.z), "f"(r.w) : "memory");
}

// ---------------- finalize: out = relu(out + b2) ----------------
__global__ void finalize_kernel(float* __restrict__ out, const float* __restrict__ b2) {
    int i = blockIdx.x * blockDim.x + threadIdx.x;
    if (i >= N_NODES * F2) return;
    out[i] = fmaxf(out[i] + b2[i & (F2 - 1)], 0.f);
}

// ---------------- host ----------------
extern "C" void kernel_launch(void* const* d_in, const int* in_sizes, int n_in,
                              void* d_out, int out_size)
{
    const float* x     = (const float*)d_in[0];
    const int*   ei    = (const int*)  d_in[1];
    const float* W1    = (const float*)d_in[2];
    const float* attS1 = (const float*)d_in[3];
    const float* attD1 = (const float*)d_in[4];
    const float* b1    = (const float*)d_in[5];
    const float* W2    = (const float*)d_in[6];
    const float* attS2 = (const float*)d_in[7];
    const float* attD2 = (const float*)d_in[8];
    const float* b2    = (const float*)d_in[9];
    float* out = (float*)d_out;

    float *h1, *as1, *ad1, *z1, *alpha1, *agg1, *h2, *as2, *ad2, *z2, *alpha2;
    int *m1, *m2;
    cudaGetSymbolAddress((void**)&h1,     g_h1);
    cudaGetSymbolAddress((void**)&as1,    g_as1);
    cudaGetSymbolAddress((void**)&ad1,    g_ad1);
    cudaGetSymbolAddress((void**)&m1,     g_m1);
    cudaGetSymbolAddress((void**)&z1,     g_z1);
    cudaGetSymbolAddress((void**)&alpha1, g_alpha1);
    cudaGetSymbolAddress((void**)&agg1,   g_agg1);
    cudaGetSymbolAddress((void**)&h2,     g_h2);
    cudaGetSymbolAddress((void**)&as2,    g_as2);
    cudaGetSymbolAddress((void**)&ad2,    g_ad2);
    cudaGetSymbolAddress((void**)&m2,     g_m2);
    cudaGetSymbolAddress((void**)&z2,     g_z2);
    cudaGetSymbolAddress((void**)&alpha2, g_alpha2);

    const int TB = 256;

    // init
    {
        int total = N_NODES * F1;
        init_kernel<<<(total + TB - 1) / TB, TB>>>(out);
    }

    // layer 1
    gemm1_kernel<<<(N_NODES + 15) / 16, 128>>>(x, W1, attS1, attD1);
    {
        int total = E_TOT * H1;
        edge_max_kernel<H1><<<(total + TB - 1) / TB, TB>>>(ei, as1, ad1, alpha1, m1);
        edge_sum_kernel<H1><<<(total + TB - 1) / TB, TB>>>(ei, m1, alpha1, z1);
        int totalC = E_TOT * (H1 * C1 / 4);
        edge_agg_kernel<H1, C1><<<(totalC + TB - 1) / TB, TB>>>(ei, h1, alpha1, z1, agg1);
    }

    // layer 2
    gemm2_kernel<<<(N_NODES + 7) / 8, 64>>>(b1, W2, attS2, attD2);
    {
        int total = E_TOT;
        edge_max_kernel<1><<<(total + TB - 1) / TB, TB>>>(ei, as2, ad2, alpha2, m2);
        edge_sum_kernel<1><<<(total + TB - 1) / TB, TB>>>(ei, m2, alpha2, z2);
        int totalC = E_TOT * (F2 / 4);
        edge_agg_kernel<1, F2><<<(totalC + TB - 1) / TB, TB>>>(ei, h2, alpha2, z2, out);
    }

    finalize_kernel<<<(N_NODES * F2 + TB - 1) / TB, TB>>>(out, b2);
}

// round 2
// speedup vs baseline: 1.0508x; 1.0508x over previous
#include <cuda_runtime.h>

#define N_NODES 50000
#define N_EDGES 800000
#define E_TOT   850000      // edges + self loops
#define F0      128
#define F1      128         // H1*C1
#define H1      4
#define C1      32
#define F2      64
#define NEG     0.2f
#define EPS_Z   1e-16f

// ---------------- scratch ----------------
__device__ float g_h1[N_NODES * F1];
__device__ float g_as1[N_NODES * H1];
__device__ float g_ad1[N_NODES * H1];
__device__ float g_agg1[N_NODES * F1];
__device__ float g_h2[N_NODES * F2];
__device__ float g_as2[N_NODES];
__device__ float g_ad2[N_NODES];
__device__ int   g_deg[N_NODES];
__device__ int   g_cur[N_NODES];
__device__ int   g_off[N_NODES + 1];
__device__ int   g_csr_src[E_TOT];

__device__ __forceinline__ float lrelu(float a) { return (a > 0.f) ? a : NEG * a; }

// ---------------- CSR build ----------------
__global__ void zero_cnt_kernel() {
    int i = blockIdx.x * blockDim.x + threadIdx.x;
    if (i < N_NODES) { g_deg[i] = 0; g_cur[i] = 0; }
}

__global__ void hist_kernel(const int* __restrict__ ei) {
    int e = blockIdx.x * blockDim.x + threadIdx.x;
    if (e >= E_TOT) return;
    int d = (e < N_EDGES) ? ei[N_EDGES + e] : (e - N_EDGES);
    atomicAdd(&g_deg[d], 1);
}

__global__ __launch_bounds__(1024) void scan_kernel() {
    __shared__ int sums[1024];
    const int t = threadIdx.x;
    const int CH = (N_NODES + 1023) / 1024;   // 49
    int base = t * CH;
    int s = 0;
    for (int i = 0; i < CH; i++) {
        int idx = base + i;
        if (idx < N_NODES) s += g_deg[idx];
    }
    sums[t] = s;
    __syncthreads();
    for (int off = 1; off < 1024; off <<= 1) {
        int v = (t >= off) ? sums[t - off] : 0;
        __syncthreads();
        sums[t] += v;
        __syncthreads();
    }
    int prefix = (t == 0) ? 0 : sums[t - 1];
    for (int i = 0; i < CH; i++) {
        int idx = base + i;
        if (idx < N_NODES) {
            int d = g_deg[idx];
            g_off[idx] = prefix;
            prefix += d;
        }
    }
    if (t == 1023) g_off[N_NODES] = sums[1023];
}

__global__ void scatter_kernel(const int* __restrict__ ei) {
    int e = blockIdx.x * blockDim.x + threadIdx.x;
    if (e >= E_TOT) return;
    int s, d;
    if (e < N_EDGES) { s = ei[e]; d = ei[N_EDGES + e]; }
    else             { s = e - N_EDGES; d = s; }
    int pos = g_off[d] + atomicAdd(&g_cur[d], 1);
    g_csr_src[pos] = s;
}

// ---------------- layer1 GEMM + attention dots ----------------
__global__ __launch_bounds__(128) void gemm1_kernel(
    const float* __restrict__ x, const float* __restrict__ W,
    const float* __restrict__ attS, const float* __restrict__ attD)
{
    __shared__ float xs[4][F0];
    __shared__ float sAs[F1], sAd[F1];
    const int j = threadIdx.x;
    sAs[j] = attS[j];
    sAd[j] = attD[j];
    const int head = j >> 5;
    const int base = blockIdx.x * 16;

    for (int g0 = 0; g0 < 16; g0 += 4) {
        __syncthreads();
        #pragma unroll
        for (int r = 0; r < 4; r++) {
            int n = base + g0 + r;
            xs[r][j] = (n < N_NODES) ? x[n * F0 + j] : 0.f;
        }
        __syncthreads();

        float acc0 = 0.f, acc1 = 0.f, acc2 = 0.f, acc3 = 0.f;
        #pragma unroll 8
        for (int k = 0; k < F0; k++) {
            float w = W[k * F1 + j];
            acc0 = fmaf(w, xs[0][k], acc0);
            acc1 = fmaf(w, xs[1][k], acc1);
            acc2 = fmaf(w, xs[2][k], acc2);
            acc3 = fmaf(w, xs[3][k], acc3);
        }

        float accs[4] = {acc0, acc1, acc2, acc3};
        #pragma unroll
        for (int r = 0; r < 4; r++) {
            int n = base + g0 + r;
            if (n >= N_NODES) break;
            float v = accs[r];
            g_h1[n * F1 + j] = v;
            float ps = v * sAs[j];
            float pd = v * sAd[j];
            #pragma unroll
            for (int off = 16; off > 0; off >>= 1) {
                ps += __shfl_down_sync(0xffffffffu, ps, off);
                pd += __shfl_down_sync(0xffffffffu, pd, off);
            }
            if ((j & 31) == 0) {
                g_as1[n * H1 + head] = ps;
                g_ad1[n * H1 + head] = pd;
            }
        }
    }
}

// ---------------- layer1 fused softmax + aggregate (warp per node) ----------------
__global__ __launch_bounds__(256) void agg1_kernel() {
    int warp = (blockIdx.x * 256 + threadIdx.x) >> 5;
    int lane = threadIdx.x & 31;
    if (warp >= N_NODES) return;
    const int n = warp;
    const int beg = g_off[n], end = g_off[n + 1];

    float4 ad = *(const float4*)&g_ad1[n * H1];

    // pass 1: per-head max (all lanes redundant; loads broadcast)
    float4 m = make_float4(-1e30f, -1e30f, -1e30f, -1e30f);
    for (int p = beg; p < end; p++) {
        int s = g_csr_src[p];
        float4 as = *(const float4*)&g_as1[s * H1];
        m.x = fmaxf(m.x, lrelu(as.x + ad.x));
        m.y = fmaxf(m.y, lrelu(as.y + ad.y));
        m.z = fmaxf(m.z, lrelu(as.z + ad.z));
        m.w = fmaxf(m.w, lrelu(as.w + ad.w));
    }

    // pass 2: exp + accumulate
    const int h = lane >> 3;                // lane's head (columns 4*lane..4*lane+3)
    float4 acc = make_float4(0.f, 0.f, 0.f, 0.f);
    float4 z   = make_float4(0.f, 0.f, 0.f, 0.f);
    for (int p = beg; p < end; p++) {
        int s = g_csr_src[p];
        float4 as = *(const float4*)&g_as1[s * H1];
        float4 e;
        e.x = __expf(lrelu(as.x + ad.x) - m.x);
        e.y = __expf(lrelu(as.y + ad.y) - m.y);
        e.z = __expf(lrelu(as.z + ad.z) - m.z);
        e.w = __expf(lrelu(as.w + ad.w) - m.w);
        z.x += e.x; z.y += e.y; z.z += e.z; z.w += e.w;
        float eh = (h == 0) ? e.x : (h == 1) ? e.y : (h == 2) ? e.z : e.w;
        float4 v = *(const float4*)&g_h1[(long)s * F1 + lane * 4];
        acc.x = fmaf(eh, v.x, acc.x);
        acc.y = fmaf(eh, v.y, acc.y);
        acc.z = fmaf(eh, v.z, acc.z);
        acc.w = fmaf(eh, v.w, acc.w);
    }
    float zh = (h == 0) ? z.x : (h == 1) ? z.y : (h == 2) ? z.z : z.w;
    float inv = 1.f / (zh + EPS_Z);
    float4 o;
    o.x = acc.x * inv; o.y = acc.y * inv; o.z = acc.z * inv; o.w = acc.w * inv;
    *(float4*)&g_agg1[(long)n * F1 + lane * 4] = o;
}

// ---------------- layer2 GEMM (input = relu(agg1 + b1)) ----------------
__global__ __launch_bounds__(64) void gemm2_kernel(
    const float* __restrict__ b1, const float* __restrict__ W,
    const float* __restrict__ attS, const float* __restrict__ attD)
{
    __shared__ float xs[F1];
    __shared__ float red[4];
    const int j = threadIdx.x;   // 0..63
    const int warp = j >> 5;
    const int base = blockIdx.x * 8;

    for (int g = 0; g < 8; g++) {
        int n = base + g;
        if (n >= N_NODES) return;
        __syncthreads();
        xs[j]      = fmaxf(g_agg1[n * F1 + j]      + b1[j],      0.f);
        xs[j + 64] = fmaxf(g_agg1[n * F1 + j + 64] + b1[j + 64], 0.f);
        __syncthreads();

        float acc = 0.f;
        #pragma unroll 8
        for (int k = 0; k < F1; k++)
            acc = fmaf(W[k * F2 + j], xs[k], acc);

        g_h2[n * F2 + j] = acc;
        float ps = acc * attS[j];
        float pd = acc * attD[j];
        #pragma unroll
        for (int off = 16; off > 0; off >>= 1) {
            ps += __shfl_down_sync(0xffffffffu, ps, off);
            pd += __shfl_down_sync(0xffffffffu, pd, off);
        }
        if ((j & 31) == 0) { red[warp] = ps; red[2 + warp] = pd; }
        __syncthreads();
        if (j == 0) {
            g_as2[n] = red[0] + red[1];
            g_ad2[n] = red[2] + red[3];
        }
    }
}

// ---------------- layer2 fused softmax + aggregate + bias + relu ----------------
__global__ __launch_bounds__(256) void agg2_kernel(float* __restrict__ out,
                                                   const float* __restrict__ b2) {
    int warp = (blockIdx.x * 256 + threadIdx.x) >> 5;
    int lane = threadIdx.x & 31;
    if (warp >= N_NODES) return;
    const int n = warp;
    const int beg = g_off[n], end = g_off[n + 1];

    float ad = g_ad2[n];

    float m = -1e30f;
    for (int p = beg; p < end; p++) {
        int s = g_csr_src[p];
        m = fmaxf(m, lrelu(g_as2[s] + ad));
    }

    float2 acc = make_float2(0.f, 0.f);
    float z = 0.f;
    for (int p = beg; p < end; p++) {
        int s = g_csr_src[p];
        float e = __expf(lrelu(g_as2[s] + ad) - m);
        z += e;
        float2 v = *(const float2*)&g_h2[(long)s * F2 + lane * 2];
        acc.x = fmaf(e, v.x, acc.x);
        acc.y = fmaf(e, v.y, acc.y);
    }
    float inv = 1.f / (z + EPS_Z);
    float2 bb = *(const float2*)&b2[lane * 2];
    float2 o;
    o.x = fmaxf(acc.x * inv + bb.x, 0.f);
    o.y = fmaxf(acc.y * inv + bb.y, 0.f);
    *(float2*)&out[(long)n * F2 + lane * 2] = o;
}

// ---------------- host ----------------
extern "C" void kernel_launch(void* const* d_in, const int* in_sizes, int n_in,
                              void* d_out, int out_size)
{
    const float* x     = (const float*)d_in[0];
    const int*   ei    = (const int*)  d_in[1];
    const float* W1    = (const float*)d_in[2];
    const float* attS1 = (const float*)d_in[3];
    const float* attD1 = (const float*)d_in[4];
    const float* b1    = (const float*)d_in[5];
    const float* W2    = (const float*)d_in[6];
    const float* attS2 = (const float*)d_in[7];
    const float* attD2 = (const float*)d_in[8];
    const float* b2    = (const float*)d_in[9];
    float* out = (float*)d_out;

    const int TB = 256;

    // CSR build (counting sort by dst)
    zero_cnt_kernel<<<(N_NODES + TB - 1) / TB, TB>>>();
    hist_kernel<<<(E_TOT + TB - 1) / TB, TB>>>(ei);
    scan_kernel<<<1, 1024>>>();
    scatter_kernel<<<(E_TOT + TB - 1) / TB, TB>>>(ei);

    // layer 1
    gemm1_kernel<<<(N_NODES + 15) / 16, 128>>>(x, W1, attS1, attD1);
    agg1_kernel<<<(N_NODES * 32 + TB - 1) / TB, TB>>>();

    // layer 2
    gemm2_kernel<<<(N_NODES + 7) / 8, 64>>>(b1, W2, attS2, attD2);
    agg2_kernel<<<(N_NODES * 32 + TB - 1) / TB, TB>>>(out, b2);
}

// round 3
// speedup vs baseline: 1.6694x; 1.5887x over previous
#include <cuda_runtime.h>

#define N_NODES 50000
#define N_EDGES 800000
#define E_TOT   850000
#define F0      128
#define F1      128
#define H1      4
#define C1      32
#define F2      64
#define NEG     0.2f
#define EPS_Z   1e-16f

#define SCAN_B  1024
#define SCAN_G  ((N_NODES + SCAN_B - 1) / SCAN_B)   // 49

typedef unsigned long long ull;

// ---------------- scratch ----------------
__device__ float g_h1[N_NODES * F1];
__device__ float g_as1[N_NODES * H1];
__device__ float g_ad1[N_NODES * H1];
__device__ float g_agg1[N_NODES * F1];
__device__ float g_h2[N_NODES * F2];
__device__ float g_as2[N_NODES];
__device__ float g_ad2[N_NODES];
__device__ int   g_deg[N_NODES];
__device__ int   g_cur[N_NODES];
__device__ int   g_off[N_NODES + 1];
__device__ int   g_bsum[SCAN_G];
__device__ int   g_bpre[SCAN_G];
__device__ int   g_csr_src[E_TOT];

__device__ __forceinline__ float lrelu(float a) { return (a > 0.f) ? a : NEG * a; }

__device__ __forceinline__ void ffma2(ull& d, ull a, ull b) {
    asm("fma.rn.f32x2 %0, %1, %2, %0;" : "+l"(d) : "l"(a), "l"(b));
}
__device__ __forceinline__ void unpack2(ull v, float& x, float& y) {
    asm("mov.b64 {%0,%1}, %2;" : "=f"(x), "=f"(y) : "l"(v));
}

// ---------------- CSR build ----------------
__global__ void zero_cnt_kernel() {
    int i = blockIdx.x * blockDim.x + threadIdx.x;
    if (i < N_NODES) { g_deg[i] = 0; g_cur[i] = 0; }
}

__global__ void hist_kernel(const int* __restrict__ ei) {
    int e = blockIdx.x * blockDim.x + threadIdx.x;
    if (e >= E_TOT) return;
    int d = (e < N_EDGES) ? ei[N_EDGES + e] : (e - N_EDGES);
    atomicAdd(&g_deg[d], 1);
}

// block-local exclusive scan, coalesced
__global__ __launch_bounds__(SCAN_B) void scan1_kernel() {
    const int t = threadIdx.x, b = blockIdx.x;
    const int lane = t & 31, warp = t >> 5;
    int i = b * SCAN_B + t;
    int v = (i < N_NODES) ? g_deg[i] : 0;
    int s = v;
    #pragma unroll
    for (int off = 1; off < 32; off <<= 1) {
        int u = __shfl_up_sync(0xffffffffu, s, off);
        if (lane >= off) s += u;
    }
    __shared__ int wsum[32];
    if (lane == 31) wsum[warp] = s;
    __syncthreads();
    if (warp == 0) {
        int ws = wsum[lane];
        #pragma unroll
        for (int off = 1; off < 32; off <<= 1) {
            int u = __shfl_up_sync(0xffffffffu, ws, off);
            if (lane >= off) ws += u;
        }
        wsum[lane] = ws;
    }
    __syncthreads();
    int add = (warp > 0) ? wsum[warp - 1] : 0;
    s += add;
    if (i < N_NODES) g_off[i] = s - v;   // exclusive, chunk-local
    if (t == SCAN_B - 1) g_bsum[b] = s;
}

__global__ void scan2_kernel() {
    if (threadIdx.x == 0) {
        int run = 0;
        for (int b = 0; b < SCAN_G; b++) { g_bpre[b] = run; run += g_bsum[b]; }
        g_off[N_NODES] = run;
    }
}

__global__ __launch_bounds__(SCAN_B) void scan3_kernel() {
    int i = blockIdx.x * SCAN_B + threadIdx.x;
    if (i < N_NODES) g_off[i] += g_bpre[blockIdx.x];
}

__global__ void scatter_kernel(const int* __restrict__ ei) {
    int e = blockIdx.x * blockDim.x + threadIdx.x;
    if (e >= E_TOT) return;
    int s, d;
    if (e < N_EDGES) { s = ei[e]; d = ei[N_EDGES + e]; }
    else             { s = e - N_EDGES; d = s; }
    int pos = g_off[d] + atomicAdd(&g_cur[d], 1);
    g_csr_src[pos] = s;
}

// ---------------- layer1 GEMM (f32x2) + attention dots ----------------
// blockDim=128: quad = t&31 (channels quad*4..+3), slot = t>>5 (nodes slot*2, slot*2+1)
__global__ __launch_bounds__(128) void gemm1_kernel(
    const float* __restrict__ x, const float* __restrict__ W,
    const float* __restrict__ attS, const float* __restrict__ attD)
{
    __shared__ float2 xs2[8][F0];
    const int t = threadIdx.x;
    const int quad = t & 31, slot = t >> 5;
    const int base = blockIdx.x * 8;

    #pragma unroll
    for (int r = 0; r < 8; r++) {
        float v = x[(long)(base + r) * F0 + t];
        xs2[r][t] = make_float2(v, v);
    }
    __syncthreads();

    const int r0 = slot * 2, r1 = slot * 2 + 1;
    ull a00 = 0, a01 = 0, a10 = 0, a11 = 0;
    const float* Wp = W + quad * 4;
    #pragma unroll 4
    for (int k = 0; k < F0; k++) {
        ulonglong2 w = *(const ulonglong2*)(Wp + (long)k * F1);
        ull xa = *(const ull*)&xs2[r0][k];
        ull xb = *(const ull*)&xs2[r1][k];
        ffma2(a00, w.x, xa); ffma2(a01, w.y, xa);
        ffma2(a10, w.x, xb); ffma2(a11, w.y, xb);
    }

    float4 aS = *(const float4*)&attS[quad * 4];
    float4 aD = *(const float4*)&attD[quad * 4];
    const int head = quad >> 3;

    ull pa[2] = {a00, a10}, pb[2] = {a01, a11};
    #pragma unroll
    for (int r = 0; r < 2; r++) {
        int n = base + slot * 2 + r;
        float v0, v1, v2, v3;
        unpack2(pa[r], v0, v1);
        unpack2(pb[r], v2, v3);
        *(float4*)&g_h1[(long)n * F1 + quad * 4] = make_float4(v0, v1, v2, v3);
        float ps = v0 * aS.x + v1 * aS.y + v2 * aS.z + v3 * aS.w;
        float pd = v0 * aD.x + v1 * aD.y + v2 * aD.z + v3 * aD.w;
        #pragma unroll
        for (int off = 4; off > 0; off >>= 1) {
            ps += __shfl_down_sync(0xffffffffu, ps, off, 8);
            pd += __shfl_down_sync(0xffffffffu, pd, off, 8);
        }
        if ((quad & 7) == 0) {
            g_as1[n * H1 + head] = ps;
            g_ad1[n * H1 + head] = pd;
        }
    }
}

// ---------------- layer1 fused softmax(no-max) + aggregate (warp/node) ----------------
__global__ __launch_bounds__(256) void agg1_kernel() {
    int warp = (blockIdx.x * 256 + threadIdx.x) >> 5;
    int lane = threadIdx.x & 31;
    if (warp >= N_NODES) return;
    const int n = warp;
    const int beg = g_off[n], end = g_off[n + 1];
    const int h = lane >> 3;

    float adh = g_ad1[n * H1 + h];
    float4 acc = make_float4(0.f, 0.f, 0.f, 0.f);
    float z = 0.f;
    for (int p = beg; p < end; p++) {
        int s = g_csr_src[p];
        float ash = g_as1[s * H1 + h];
        float e = __expf(lrelu(ash + adh));
        z += e;
        float4 v = *(const float4*)&g_h1[(long)s * F1 + lane * 4];
        acc.x = fmaf(e, v.x, acc.x);
        acc.y = fmaf(e, v.y, acc.y);
        acc.z = fmaf(e, v.z, acc.z);
        acc.w = fmaf(e, v.w, acc.w);
    }
    float inv = 1.f / (z + EPS_Z);
    float4 o;
    o.x = acc.x * inv; o.y = acc.y * inv; o.z = acc.z * inv; o.w = acc.w * inv;
    *(float4*)&g_agg1[(long)n * F1 + lane * 4] = o;
}

// ---------------- layer2 GEMM (f32x2, input = relu(agg1+b1)) ----------------
// blockDim=128: quad = t&15 (channels quad*4..+3 of 64), slot = t>>4 (node slot), 8 nodes/block
__global__ __launch_bounds__(128) void gemm2_kernel(
    const float* __restrict__ b1, const float* __restrict__ W,
    const float* __restrict__ attS, const float* __restrict__ attD)
{
    __shared__ float2 xs2[8][F1];
    const int t = threadIdx.x;
    const int quad = t & 15, slot = t >> 4;
    const int base = blockIdx.x * 8;

    #pragma unroll
    for (int r = 0; r < 8; r++) {
        float v = fmaxf(g_agg1[(long)(base + r) * F1 + t] + b1[t], 0.f);
        xs2[r][t] = make_float2(v, v);
    }
    __syncthreads();

    const int n = base + slot;
    ull a0 = 0, a1 = 0;
    const float* Wp = W + quad * 4;
    #pragma unroll 4
    for (int k = 0; k < F1; k++) {
        ulonglong2 w = *(const ulonglong2*)(Wp + (long)k * F2);
        ull xv = *(const ull*)&xs2[slot][k];
        ffma2(a0, w.x, xv); ffma2(a1, w.y, xv);
    }

    float4 aS = *(const float4*)&attS[quad * 4];
    float4 aD = *(const float4*)&attD[quad * 4];
    float v0, v1, v2, v3;
    unpack2(a0, v0, v1);
    unpack2(a1, v2, v3);
    *(float4*)&g_h2[(long)n * F2 + quad * 4] = make_float4(v0, v1, v2, v3);
    float ps = v0 * aS.x + v1 * aS.y + v2 * aS.z + v3 * aS.w;
    float pd = v0 * aD.x + v1 * aD.y + v2 * aD.z + v3 * aD.w;
    #pragma unroll
    for (int off = 8; off > 0; off >>= 1) {
        ps += __shfl_down_sync(0xffffffffu, ps, off, 16);
        pd += __shfl_down_sync(0xffffffffu, pd, off, 16);
    }
    if (quad == 0) {
        g_as2[n] = ps;
        g_ad2[n] = pd;
    }
}

// ---------------- layer2 fused softmax(no-max) + aggregate + bias + relu ----------------
__global__ __launch_bounds__(256) void agg2_kernel(float* __restrict__ out,
                                                   const float* __restrict__ b2) {
    int warp = (blockIdx.x * 256 + threadIdx.x) >> 5;
    int lane = threadIdx.x & 31;
    if (warp >= N_NODES) return;
    const int n = warp;
    const int beg = g_off[n], end = g_off[n + 1];

    float ad = g_ad2[n];
    float2 acc = make_float2(0.f, 0.f);
    float z = 0.f;
    for (int p = beg; p < end; p++) {
        int s = g_csr_src[p];
        float e = __expf(lrelu(g_as2[s] + ad));
        z += e;
        float2 v = *(const float2*)&g_h2[(long)s * F2 + lane * 2];
        acc.x = fmaf(e, v.x, acc.x);
        acc.y = fmaf(e, v.y, acc.y);
    }
    float inv = 1.f / (z + EPS_Z);
    float2 bb = *(const float2*)&b2[lane * 2];
    float2 o;
    o.x = fmaxf(acc.x * inv + bb.x, 0.f);
    o.y = fmaxf(acc.y * inv + bb.y, 0.f);
    *(float2*)&out[(long)n * F2 + lane * 2] = o;
}

// ---------------- host ----------------
extern "C" void kernel_launch(void* const* d_in, const int* in_sizes, int n_in,
                              void* d_out, int out_size)
{
    const float* x     = (const float*)d_in[0];
    const int*   ei    = (const int*)  d_in[1];
    const float* W1    = (const float*)d_in[2];
    const float* attS1 = (const float*)d_in[3];
    const float* attD1 = (const float*)d_in[4];
    const float* b1    = (const float*)d_in[5];
    const float* W2    = (const float*)d_in[6];
    const float* attS2 = (const float*)d_in[7];
    const float* attD2 = (const float*)d_in[8];
    const float* b2    = (const float*)d_in[9];
    float* out = (float*)d_out;

    const int TB = 256;

    // CSR build
    zero_cnt_kernel<<<(N_NODES + TB - 1) / TB, TB>>>();
    hist_kernel<<<(E_TOT + TB - 1) / TB, TB>>>(ei);
    scan1_kernel<<<SCAN_G, SCAN_B>>>();
    scan2_kernel<<<1, 32>>>();
    scan3_kernel<<<SCAN_G, SCAN_B>>>();
    scatter_kernel<<<(E_TOT + TB - 1) / TB, TB>>>(ei);

    // layer 1
    gemm1_kernel<<<N_NODES / 8, 128>>>(x, W1, attS1, attD1);
    agg1_kernel<<<(N_NODES * 32 + TB - 1) / TB, TB>>>();

    // layer 2
    gemm2_kernel<<<N_NODES / 8, 128>>>(b1, W2, attS2, attD2);
    agg2_kernel<<<(N_NODES * 32 + TB - 1) / TB, TB>>>(out, b2);
}

// round 4
// speedup vs baseline: 1.7277x; 1.0350x over previous
#include <cuda_runtime.h>

#define N_NODES 50000
#define N_EDGES 800000
#define E_TOT   850000
#define F0      128
#define F1      128
#define H1      4
#define C1      32
#define F2      64
#define NEG     0.2f
#define EPS_Z   1e-16f

#define SCAN_B  1024
#define SCAN_G  ((N_NODES + SCAN_B - 1) / SCAN_B)   // 49

typedef unsigned long long ull;

// ---------------- scratch ----------------
__device__ float g_h1[N_NODES * F1];
__device__ float g_as1[N_NODES * H1];
__device__ float g_ad1[N_NODES * H1];
__device__ float g_agg1[N_NODES * F1];
__device__ float g_h2[N_NODES * F2];
__device__ float g_as2[N_NODES];
__device__ float g_ad2[N_NODES];
__device__ int   g_deg[N_NODES];
__device__ int   g_cur[N_NODES];          // running scatter cursor
__device__ int   g_off[N_NODES + 1];
__device__ int   g_bsum[SCAN_G];
__device__ int   g_bpre[SCAN_G];
__device__ int   g_csr_src[E_TOT];

__device__ __forceinline__ float lrelu(float a) { return (a > 0.f) ? a : NEG * a; }

__device__ __forceinline__ void ffma2(ull& d, ull a, ull b) {
    asm("fma.rn.f32x2 %0, %1, %2, %0;" : "+l"(d) : "l"(a), "l"(b));
}
__device__ __forceinline__ void unpack2(ull v, float& x, float& y) {
    asm("mov.b64 {%0,%1}, %2;" : "=f"(x), "=f"(y) : "l"(v));
}

// ---------------- CSR build ----------------
__global__ void zero_cnt_kernel() {
    int i = blockIdx.x * blockDim.x + threadIdx.x;
    if (i < N_NODES) g_deg[i] = 1;        // self loop pre-counted
}

__global__ void hist_kernel(const int* __restrict__ ei) {
    int e = blockIdx.x * blockDim.x + threadIdx.x;
    if (e >= N_EDGES) return;
    atomicAdd(&g_deg[ei[N_EDGES + e]], 1);
}

// block-local exclusive scan, coalesced
__global__ __launch_bounds__(SCAN_B) void scan1_kernel() {
    const int t = threadIdx.x, b = blockIdx.x;
    const int lane = t & 31, warp = t >> 5;
    int i = b * SCAN_B + t;
    int v = (i < N_NODES) ? g_deg[i] : 0;
    int s = v;
    #pragma unroll
    for (int off = 1; off < 32; off <<= 1) {
        int u = __shfl_up_sync(0xffffffffu, s, off);
        if (lane >= off) s += u;
    }
    __shared__ int wsum[32];
    if (lane == 31) wsum[warp] = s;
    __syncthreads();
    if (warp == 0) {
        int ws = wsum[lane];
        #pragma unroll
        for (int off = 1; off < 32; off <<= 1) {
            int u = __shfl_up_sync(0xffffffffu, ws, off);
            if (lane >= off) ws += u;
        }
        wsum[lane] = ws;
    }
    __syncthreads();
    int add = (warp > 0) ? wsum[warp - 1] : 0;
    s += add;
    if (i < N_NODES) g_off[i] = s - v;   // exclusive, chunk-local
    if (t == SCAN_B - 1) g_bsum[b] = s;
}

__global__ void scan2_kernel() {
    const int t = threadIdx.x;           // 64 threads
    __shared__ int sh[64];
    int v = (t < SCAN_G) ? g_bsum[t] : 0;
    sh[t] = v;
    __syncthreads();
    #pragma unroll
    for (int off = 1; off < 64; off <<= 1) {
        int u = (t >= off) ? sh[t - off] : 0;
        __syncthreads();
        sh[t] += u;
        __syncthreads();
    }
    if (t < SCAN_G) g_bpre[t] = sh[t] - v;
    if (t == 63) g_off[N_NODES] = sh[63];
}

// add block prefixes, emit self-loop entry, seed cursor
__global__ __launch_bounds__(SCAN_B) void scan3_kernel() {
    int i = blockIdx.x * SCAN_B + threadIdx.x;
    if (i >= N_NODES) return;
    int o = g_off[i] + g_bpre[blockIdx.x];
    g_off[i] = o;
    g_csr_src[o] = i;     // self loop occupies first slot of segment
    g_cur[i] = o + 1;
}

__global__ void scatter_kernel(const int* __restrict__ ei) {
    int e = blockIdx.x * blockDim.x + threadIdx.x;
    if (e >= N_EDGES) return;
    int s = ei[e];
    int d = ei[N_EDGES + e];
    int pos = atomicAdd(&g_cur[d], 1);
    g_csr_src[pos] = s;
}

// ---------------- layer1 GEMM (f32x2) + attention dots ----------------
__global__ __launch_bounds__(128) void gemm1_kernel(
    const float* __restrict__ x, const float* __restrict__ W,
    const float* __restrict__ attS, const float* __restrict__ attD)
{
    __shared__ float2 xs2[8][F0];
    const int t = threadIdx.x;
    const int quad = t & 31, slot = t >> 5;
    const int base = blockIdx.x * 8;

    #pragma unroll
    for (int r = 0; r < 8; r++) {
        float v = x[(long)(base + r) * F0 + t];
        xs2[r][t] = make_float2(v, v);
    }
    __syncthreads();

    const int r0 = slot * 2, r1 = slot * 2 + 1;
    ull a00 = 0, a01 = 0, a10 = 0, a11 = 0;
    const float* Wp = W + quad * 4;
    #pragma unroll 4
    for (int k = 0; k < F0; k++) {
        ulonglong2 w = *(const ulonglong2*)(Wp + (long)k * F1);
        ull xa = *(const ull*)&xs2[r0][k];
        ull xb = *(const ull*)&xs2[r1][k];
        ffma2(a00, w.x, xa); ffma2(a01, w.y, xa);
        ffma2(a10, w.x, xb); ffma2(a11, w.y, xb);
    }

    float4 aS = *(const float4*)&attS[quad * 4];
    float4 aD = *(const float4*)&attD[quad * 4];
    const int head = quad >> 3;

    ull pa[2] = {a00, a10}, pb[2] = {a01, a11};
    #pragma unroll
    for (int r = 0; r < 2; r++) {
        int n = base + slot * 2 + r;
        float v0, v1, v2, v3;
        unpack2(pa[r], v0, v1);
        unpack2(pb[r], v2, v3);
        *(float4*)&g_h1[(long)n * F1 + quad * 4] = make_float4(v0, v1, v2, v3);
        float ps = v0 * aS.x + v1 * aS.y + v2 * aS.z + v3 * aS.w;
        float pd = v0 * aD.x + v1 * aD.y + v2 * aD.z + v3 * aD.w;
        #pragma unroll
        for (int off = 4; off > 0; off >>= 1) {
            ps += __shfl_down_sync(0xffffffffu, ps, off, 8);
            pd += __shfl_down_sync(0xffffffffu, pd, off, 8);
        }
        if ((quad & 7) == 0) {
            g_as1[n * H1 + head] = ps;
            g_ad1[n * H1 + head] = pd;
        }
    }
}

// ---------------- layer1 fused softmax(no-max) + aggregate (warp/node) ----------------
__global__ __launch_bounds__(256) void agg1_kernel() {
    int warp = (blockIdx.x * 256 + threadIdx.x) >> 5;
    int lane = threadIdx.x & 31;
    if (warp >= N_NODES) return;
    const int n = warp;
    const int beg = g_off[n], end = g_off[n + 1];
    const int h = lane >> 3;

    float adh = g_ad1[n * H1 + h];
    float4 acc = make_float4(0.f, 0.f, 0.f, 0.f);
    float z = 0.f;
    for (int p = beg; p < end; p++) {
        int s = g_csr_src[p];
        float ash = g_as1[s * H1 + h];
        float e = __expf(lrelu(ash + adh));
        z += e;
        float4 v = *(const float4*)&g_h1[(long)s * F1 + lane * 4];
        acc.x = fmaf(e, v.x, acc.x);
        acc.y = fmaf(e, v.y, acc.y);
        acc.z = fmaf(e, v.z, acc.z);
        acc.w = fmaf(e, v.w, acc.w);
    }
    float inv = 1.f / (z + EPS_Z);
    float4 o;
    o.x = acc.x * inv; o.y = acc.y * inv; o.z = acc.z * inv; o.w = acc.w * inv;
    *(float4*)&g_agg1[(long)n * F1 + lane * 4] = o;
}

// ---------------- layer2 GEMM (f32x2, input = relu(agg1+b1)) ----------------
__global__ __launch_bounds__(128) void gemm2_kernel(
    const float* __restrict__ b1, const float* __restrict__ W,
    const float* __restrict__ attS, const float* __restrict__ attD)
{
    __shared__ float2 xs2[8][F1];
    const int t = threadIdx.x;
    const int quad = t & 15, slot = t >> 4;
    const int base = blockIdx.x * 8;

    #pragma unroll
    for (int r = 0; r < 8; r++) {
        float v = fmaxf(g_agg1[(long)(base + r) * F1 + t] + b1[t], 0.f);
        xs2[r][t] = make_float2(v, v);
    }
    __syncthreads();

    const int n = base + slot;
    ull a0 = 0, a1 = 0;
    const float* Wp = W + quad * 4;
    #pragma unroll 4
    for (int k = 0; k < F1; k++) {
        ulonglong2 w = *(const ulonglong2*)(Wp + (long)k * F2);
        ull xv = *(const ull*)&xs2[slot][k];
        ffma2(a0, w.x, xv); ffma2(a1, w.y, xv);
    }

    float4 aS = *(const float4*)&attS[quad * 4];
    float4 aD = *(const float4*)&attD[quad * 4];
    float v0, v1, v2, v3;
    unpack2(a0, v0, v1);
    unpack2(a1, v2, v3);
    *(float4*)&g_h2[(long)n * F2 + quad * 4] = make_float4(v0, v1, v2, v3);
    float ps = v0 * aS.x + v1 * aS.y + v2 * aS.z + v3 * aS.w;
    float pd = v0 * aD.x + v1 * aD.y + v2 * aD.z + v3 * aD.w;
    #pragma unroll
    for (int off = 8; off > 0; off >>= 1) {
        ps += __shfl_down_sync(0xffffffffu, ps, off, 16);
        pd += __shfl_down_sync(0xffffffffu, pd, off, 16);
    }
    if (quad == 0) {
        g_as2[n] = ps;
        g_ad2[n] = pd;
    }
}

// ---------------- layer2 fused softmax(no-max) + aggregate + bias + relu ----------------
__global__ __launch_bounds__(256) void agg2_kernel(float* __restrict__ out,
                                                   const float* __restrict__ b2) {
    int warp = (blockIdx.x * 256 + threadIdx.x) >> 5;
    int lane = threadIdx.x & 31;
    if (warp >= N_NODES) return;
    const int n = warp;
    const int beg = g_off[n], end = g_off[n + 1];

    float ad = g_ad2[n];
    float2 acc = make_float2(0.f, 0.f);
    float z = 0.f;
    for (int p = beg; p < end; p++) {
        int s = g_csr_src[p];
        float e = __expf(lrelu(g_as2[s] + ad));
        z += e;
        float2 v = *(const float2*)&g_h2[(long)s * F2 + lane * 2];
        acc.x = fmaf(e, v.x, acc.x);
        acc.y = fmaf(e, v.y, acc.y);
    }
    float inv = 1.f / (z + EPS_Z);
    float2 bb = *(const float2*)&b2[lane * 2];
    float2 o;
    o.x = fmaxf(acc.x * inv + bb.x, 0.f);
    o.y = fmaxf(acc.y * inv + bb.y, 0.f);
    *(float2*)&out[(long)n * F2 + lane * 2] = o;
}

// ---------------- host ----------------
extern "C" void kernel_launch(void* const* d_in, const int* in_sizes, int n_in,
                              void* d_out, int out_size)
{
    const float* x     = (const float*)d_in[0];
    const int*   ei    = (const int*)  d_in[1];
    const float* W1    = (const float*)d_in[2];
    const float* attS1 = (const float*)d_in[3];
    const float* attD1 = (const float*)d_in[4];
    const float* b1    = (const float*)d_in[5];
    const float* W2    = (const float*)d_in[6];
    const float* attS2 = (const float*)d_in[7];
    const float* attD2 = (const float*)d_in[8];
    const float* b2    = (const float*)d_in[9];
    float* out = (float*)d_out;

    // one-time stream/event setup (first call is the non-captured correctness run)
    static cudaStream_t s2 = nullptr;
    static cudaEvent_t evFork = nullptr, evJoin = nullptr;
    if (!s2) {
        cudaStreamCreateWithFlags(&s2, cudaStreamNonBlocking);
        cudaEventCreateWithFlags(&evFork, cudaEventDisableTiming);
        cudaEventCreateWithFlags(&evJoin, cudaEventDisableTiming);
    }

    const int TB = 256;

    // fork: gemm1 runs on s2 concurrently with the CSR build on the main stream
    cudaEventRecord(evFork, 0);
    cudaStreamWaitEvent(s2, evFork, 0);
    gemm1_kernel<<<N_NODES / 8, 128, 0, s2>>>(x, W1, attS1, attD1);
    cudaEventRecord(evJoin, s2);

    // CSR build (main stream)
    zero_cnt_kernel<<<(N_NODES + TB - 1) / TB, TB>>>();
    hist_kernel<<<(N_EDGES + TB - 1) / TB, TB>>>(ei);
    scan1_kernel<<<SCAN_G, SCAN_B>>>();
    scan2_kernel<<<1, 64>>>();
    scan3_kernel<<<SCAN_G, SCAN_B>>>();
    scatter_kernel<<<(N_EDGES + TB - 1) / TB, TB>>>(ei);

    // join: agg1 needs both gemm1 (h1, as1, ad1) and the CSR
    cudaStreamWaitEvent(0, evJoin, 0);
    agg1_kernel<<<(N_NODES * 32 + TB - 1) / TB, TB>>>();

    // layer 2
    gemm2_kernel<<<N_NODES / 8, 128>>>(b1, W2, attS2, attD2);
    agg2_kernel<<<(N_NODES * 32 + TB - 1) / TB, TB>>>(out, b2);
}

// round 5
// speedup vs baseline: 1.7799x; 1.0302x over previous
#include <cuda_runtime.h>
#include <cuda_fp16.h>

#define N_NODES 50000
#define N_EDGES 800000
#define E_TOT   850000
#define F0      128
#define F1      128
#define H1      4
#define C1      32
#define F2      64
#define NEG     0.2f
#define EPS_Z   1e-16f

#define SCAN_B  1024
#define SCAN_G  ((N_NODES + SCAN_B - 1) / SCAN_B)   // 49

typedef unsigned long long ull;

// ---------------- scratch ----------------
__device__ __half g_h1h[N_NODES * F1];    // fp16 features for gather
__device__ float  g_as1[N_NODES * H1];
__device__ float  g_ad1[N_NODES * H1];
__device__ float  g_agg1[N_NODES * F1];
__device__ __half g_h2h[N_NODES * F2];
__device__ float  g_as2[N_NODES];
__device__ float  g_ad2[N_NODES];
__device__ int    g_deg[N_NODES];
__device__ int    g_cur[N_NODES];
__device__ int    g_off[N_NODES + 1];
__device__ int    g_bsum[SCAN_G];
__device__ int    g_bpre[SCAN_G];
__device__ int    g_csr_src[E_TOT];

__device__ __forceinline__ float lrelu(float a) { return (a > 0.f) ? a : NEG * a; }

__device__ __forceinline__ void ffma2(ull& d, ull a, ull b) {
    asm("fma.rn.f32x2 %0, %1, %2, %0;" : "+l"(d) : "l"(a), "l"(b));
}
__device__ __forceinline__ void unpack2(ull v, float& x, float& y) {
    asm("mov.b64 {%0,%1}, %2;" : "=f"(x), "=f"(y) : "l"(v));
}

// ---------------- CSR build ----------------
__global__ void zero_cnt_kernel() {
    int i = blockIdx.x * blockDim.x + threadIdx.x;
    if (i < N_NODES) g_deg[i] = 1;        // self loop pre-counted
}

__global__ void hist_kernel(const int* __restrict__ ei) {
    int e = blockIdx.x * blockDim.x + threadIdx.x;
    if (e >= N_EDGES) return;
    atomicAdd(&g_deg[ei[N_EDGES + e]], 1);
}

__global__ __launch_bounds__(SCAN_B) void scan1_kernel() {
    const int t = threadIdx.x, b = blockIdx.x;
    const int lane = t & 31, warp = t >> 5;
    int i = b * SCAN_B + t;
    int v = (i < N_NODES) ? g_deg[i] : 0;
    int s = v;
    #pragma unroll
    for (int off = 1; off < 32; off <<= 1) {
        int u = __shfl_up_sync(0xffffffffu, s, off);
        if (lane >= off) s += u;
    }
    __shared__ int wsum[32];
    if (lane == 31) wsum[warp] = s;
    __syncthreads();
    if (warp == 0) {
        int ws = wsum[lane];
        #pragma unroll
        for (int off = 1; off < 32; off <<= 1) {
            int u = __shfl_up_sync(0xffffffffu, ws, off);
            if (lane >= off) ws += u;
        }
        wsum[lane] = ws;
    }
    __syncthreads();
    int add = (warp > 0) ? wsum[warp - 1] : 0;
    s += add;
    if (i < N_NODES) g_off[i] = s - v;
    if (t == SCAN_B - 1) g_bsum[b] = s;
}

__global__ void scan2_kernel() {
    const int t = threadIdx.x;           // 64 threads
    __shared__ int sh[64];
    int v = (t < SCAN_G) ? g_bsum[t] : 0;
    sh[t] = v;
    __syncthreads();
    #pragma unroll
    for (int off = 1; off < 64; off <<= 1) {
        int u = (t >= off) ? sh[t - off] : 0;
        __syncthreads();
        sh[t] += u;
        __syncthreads();
    }
    if (t < SCAN_G) g_bpre[t] = sh[t] - v;
    if (t == 63) g_off[N_NODES] = sh[63];
}

__global__ __launch_bounds__(SCAN_B) void scan3_kernel() {
    int i = blockIdx.x * SCAN_B + threadIdx.x;
    if (i >= N_NODES) return;
    int o = g_off[i] + g_bpre[blockIdx.x];
    g_off[i] = o;
    g_csr_src[o] = i;     // self loop in first slot
    g_cur[i] = o + 1;
}

__global__ void scatter_kernel(const int* __restrict__ ei) {
    int e = blockIdx.x * blockDim.x + threadIdx.x;
    if (e >= N_EDGES) return;
    int s = ei[e];
    int d = ei[N_EDGES + e];
    int pos = atomicAdd(&g_cur[d], 1);
    g_csr_src[pos] = s;
}

// ---------------- layer1 GEMM (f32x2) + attention dots, fp16 feature store ----------------
__global__ __launch_bounds__(128) void gemm1_kernel(
    const float* __restrict__ x, const float* __restrict__ W,
    const float* __restrict__ attS, const float* __restrict__ attD)
{
    __shared__ float2 xs2[8][F0];
    const int t = threadIdx.x;
    const int quad = t & 31, slot = t >> 5;
    const int base = blockIdx.x * 8;

    #pragma unroll
    for (int r = 0; r < 8; r++) {
        float v = x[(long)(base + r) * F0 + t];
        xs2[r][t] = make_float2(v, v);
    }
    __syncthreads();

    const int r0 = slot * 2, r1 = slot * 2 + 1;
    ull a00 = 0, a01 = 0, a10 = 0, a11 = 0;
    const float* Wp = W + quad * 4;
    #pragma unroll 4
    for (int k = 0; k < F0; k++) {
        ulonglong2 w = *(const ulonglong2*)(Wp + (long)k * F1);
        ull xa = *(const ull*)&xs2[r0][k];
        ull xb = *(const ull*)&xs2[r1][k];
        ffma2(a00, w.x, xa); ffma2(a01, w.y, xa);
        ffma2(a10, w.x, xb); ffma2(a11, w.y, xb);
    }

    float4 aS = *(const float4*)&attS[quad * 4];
    float4 aD = *(const float4*)&attD[quad * 4];
    const int head = quad >> 3;

    ull pa[2] = {a00, a10}, pb[2] = {a01, a11};
    #pragma unroll
    for (int r = 0; r < 2; r++) {
        int n = base + slot * 2 + r;
        float v0, v1, v2, v3;
        unpack2(pa[r], v0, v1);
        unpack2(pb[r], v2, v3);
        __half2 h01 = __floats2half2_rn(v0, v1);
        __half2 h23 = __floats2half2_rn(v2, v3);
        uint2 pk;
        pk.x = *(unsigned*)&h01;
        pk.y = *(unsigned*)&h23;
        *(uint2*)&g_h1h[(long)n * F1 + quad * 4] = pk;
        float ps = v0 * aS.x + v1 * aS.y + v2 * aS.z + v3 * aS.w;
        float pd = v0 * aD.x + v1 * aD.y + v2 * aD.z + v3 * aD.w;
        #pragma unroll
        for (int off = 4; off > 0; off >>= 1) {
            ps += __shfl_down_sync(0xffffffffu, ps, off, 8);
            pd += __shfl_down_sync(0xffffffffu, pd, off, 8);
        }
        if ((quad & 7) == 0) {
            g_as1[n * H1 + head] = ps;
            g_ad1[n * H1 + head] = pd;
        }
    }
}

// ---------------- layer1 fused softmax(no-max) + aggregate (warp/node, fp16 gather) ----
__global__ __launch_bounds__(256) void agg1_kernel() {
    int warp = (blockIdx.x * 256 + threadIdx.x) >> 5;
    int lane = threadIdx.x & 31;
    if (warp >= N_NODES) return;
    const int n = warp;
    const int beg = g_off[n], end = g_off[n + 1];
    const int h = lane >> 3;

    float adh = g_ad1[n * H1 + h];
    float4 acc = make_float4(0.f, 0.f, 0.f, 0.f);
    float z = 0.f;
    for (int p = beg; p < end; p++) {
        int s = g_csr_src[p];
        float ash = g_as1[s * H1 + h];
        float e = __expf(lrelu(ash + adh));
        z += e;
        uint2 pk = *(const uint2*)&g_h1h[(long)s * F1 + lane * 4];
        float2 f01 = __half22float2(*(__half2*)&pk.x);
        float2 f23 = __half22float2(*(__half2*)&pk.y);
        acc.x = fmaf(e, f01.x, acc.x);
        acc.y = fmaf(e, f01.y, acc.y);
        acc.z = fmaf(e, f23.x, acc.z);
        acc.w = fmaf(e, f23.y, acc.w);
    }
    float inv = 1.f / (z + EPS_Z);
    float4 o;
    o.x = acc.x * inv; o.y = acc.y * inv; o.z = acc.z * inv; o.w = acc.w * inv;
    *(float4*)&g_agg1[(long)n * F1 + lane * 4] = o;
}

// ---------------- layer2 GEMM (f32x2, input = relu(agg1+b1)), fp16 store ----------------
__global__ __launch_bounds__(128) void gemm2_kernel(
    const float* __restrict__ b1, const float* __restrict__ W,
    const float* __restrict__ attS, const float* __restrict__ attD)
{
    __shared__ float2 xs2[8][F1];
    const int t = threadIdx.x;
    const int quad = t & 15, slot = t >> 4;
    const int base = blockIdx.x * 8;

    #pragma unroll
    for (int r = 0; r < 8; r++) {
        float v = fmaxf(g_agg1[(long)(base + r) * F1 + t] + b1[t], 0.f);
        xs2[r][t] = make_float2(v, v);
    }
    __syncthreads();

    const int n = base + slot;
    ull a0 = 0, a1 = 0;
    const float* Wp = W + quad * 4;
    #pragma unroll 4
    for (int k = 0; k < F1; k++) {
        ulonglong2 w = *(const ulonglong2*)(Wp + (long)k * F2);
        ull xv = *(const ull*)&xs2[slot][k];
        ffma2(a0, w.x, xv); ffma2(a1, w.y, xv);
    }

    float4 aS = *(const float4*)&attS[quad * 4];
    float4 aD = *(const float4*)&attD[quad * 4];
    float v0, v1, v2, v3;
    unpack2(a0, v0, v1);
    unpack2(a1, v2, v3);
    __half2 h01 = __floats2half2_rn(v0, v1);
    __half2 h23 = __floats2half2_rn(v2, v3);
    uint2 pk;
    pk.x = *(unsigned*)&h01;
    pk.y = *(unsigned*)&h23;
    *(uint2*)&g_h2h[(long)n * F2 + quad * 4] = pk;
    float ps = v0 * aS.x + v1 * aS.y + v2 * aS.z + v3 * aS.w;
    float pd = v0 * aD.x + v1 * aD.y + v2 * aD.z + v3 * aD.w;
    #pragma unroll
    for (int off = 8; off > 0; off >>= 1) {
        ps += __shfl_down_sync(0xffffffffu, ps, off, 16);
        pd += __shfl_down_sync(0xffffffffu, pd, off, 16);
    }
    if (quad == 0) {
        g_as2[n] = ps;
        g_ad2[n] = pd;
    }
}

// ---------------- layer2 fused softmax + aggregate + bias + relu (fp16 gather) --------
__global__ __launch_bounds__(256) void agg2_kernel(float* __restrict__ out,
                                                   const float* __restrict__ b2) {
    int warp = (blockIdx.x * 256 + threadIdx.x) >> 5;
    int lane = threadIdx.x & 31;
    if (warp >= N_NODES) return;
    const int n = warp;
    const int beg = g_off[n], end = g_off[n + 1];

    float ad = g_ad2[n];
    float2 acc = make_float2(0.f, 0.f);
    float z = 0.f;
    for (int p = beg; p < end; p++) {
        int s = g_csr_src[p];
        float e = __expf(lrelu(g_as2[s] + ad));
        z += e;
        unsigned pk = *(const unsigned*)&g_h2h[(long)s * F2 + lane * 2];
        float2 v = __half22float2(*(__half2*)&pk);
        acc.x = fmaf(e, v.x, acc.x);
        acc.y = fmaf(e, v.y, acc.y);
    }
    float inv = 1.f / (z + EPS_Z);
    float2 bb = *(const float2*)&b2[lane * 2];
    float2 o;
    o.x = fmaxf(acc.x * inv + bb.x, 0.f);
    o.y = fmaxf(acc.y * inv + bb.y, 0.f);
    *(float2*)&out[(long)n * F2 + lane * 2] = o;
}

// ---------------- host ----------------
extern "C" void kernel_launch(void* const* d_in, const int* in_sizes, int n_in,
                              void* d_out, int out_size)
{
    const float* x     = (const float*)d_in[0];
    const int*   ei    = (const int*)  d_in[1];
    const float* W1    = (const float*)d_in[2];
    const float* attS1 = (const float*)d_in[3];
    const float* attD1 = (const float*)d_in[4];
    const float* b1    = (const float*)d_in[5];
    const float* W2    = (const float*)d_in[6];
    const float* attS2 = (const float*)d_in[7];
    const float* attD2 = (const float*)d_in[8];
    const float* b2    = (const float*)d_in[9];
    float* out = (float*)d_out;

    static cudaStream_t s2 = nullptr;
    static cudaEvent_t evFork = nullptr, evJoin = nullptr;
    if (!s2) {
        cudaStreamCreateWithFlags(&s2, cudaStreamNonBlocking);
        cudaEventCreateWithFlags(&evFork, cudaEventDisableTiming);
        cudaEventCreateWithFlags(&evJoin, cudaEventDisableTiming);
    }

    const int TB = 256;

    // fork: gemm1 overlaps the CSR build
    cudaEventRecord(evFork, 0);
    cudaStreamWaitEvent(s2, evFork, 0);
    gemm1_kernel<<<N_NODES / 8, 128, 0, s2>>>(x, W1, attS1, attD1);
    cudaEventRecord(evJoin, s2);

    // CSR build (main stream)
    zero_cnt_kernel<<<(N_NODES + TB - 1) / TB, TB>>>();
    hist_kernel<<<(N_EDGES + TB - 1) / TB, TB>>>(ei);
    scan1_kernel<<<SCAN_G, SCAN_B>>>();
    scan2_kernel<<<1, 64>>>();
    scan3_kernel<<<SCAN_G, SCAN_B>>>();
    scatter_kernel<<<(N_EDGES + TB - 1) / TB, TB>>>(ei);

    cudaStreamWaitEvent(0, evJoin, 0);
    agg1_kernel<<<(N_NODES * 32 + TB - 1) / TB, TB>>>();

    gemm2_kernel<<<N_NODES / 8, 128>>>(b1, W2, attS2, attD2);
    agg2_kernel<<<(N_NODES * 32 + TB - 1) / TB, TB>>>(out, b2);
}

// round 6
// speedup vs baseline: 1.7818x; 1.0011x over previous
#include <cuda_runtime.h>
#include <cuda_fp16.h>

#define N_NODES 50000
#define N_EDGES 800000
#define E_TOT   850000
#define F0      128
#define F1      128
#define H1      4
#define C1      32
#define F2      64
#define NEG     0.2f
#define EPS_Z   1e-16f

#define SCAN_B  1024
#define SCAN_G  ((N_NODES + SCAN_B - 1) / SCAN_B)   // 49

typedef unsigned long long ull;

// ---------------- scratch ----------------
__device__ __half g_h1h[N_NODES * F1];
__device__ float  g_as1[N_NODES * H1];
__device__ float  g_ad1[N_NODES * H1];
__device__ float  g_agg1[N_NODES * F1];
__device__ __half g_h2h[N_NODES * F2];
__device__ float  g_as2[N_NODES];
__device__ float  g_ad2[N_NODES];
__device__ int    g_deg[N_NODES];
__device__ int    g_cur[N_NODES];
__device__ int    g_off[N_NODES + 1];
__device__ int    g_bsum[SCAN_G];
__device__ int    g_bpre[SCAN_G];
__device__ int    g_csr_src[E_TOT];

__device__ __forceinline__ float lrelu(float a) { return (a > 0.f) ? a : NEG * a; }

__device__ __forceinline__ void ffma2(ull& d, ull a, ull b) {
    asm("fma.rn.f32x2 %0, %1, %2, %0;" : "+l"(d) : "l"(a), "l"(b));
}
__device__ __forceinline__ void unpack2(ull v, float& x, float& y) {
    asm("mov.b64 {%0,%1}, %2;" : "=f"(x), "=f"(y) : "l"(v));
}

// ---------------- CSR build ----------------
__global__ void zero_cnt_kernel() {
    int i = blockIdx.x * blockDim.x + threadIdx.x;
    if (i < N_NODES) g_deg[i] = 1;        // self loop pre-counted
}

__global__ void hist_kernel(const int* __restrict__ ei) {
    int e = blockIdx.x * blockDim.x + threadIdx.x;
    if (e >= N_EDGES) return;
    atomicAdd(&g_deg[ei[N_EDGES + e]], 1);
}

__global__ __launch_bounds__(SCAN_B) void scan1_kernel() {
    const int t = threadIdx.x, b = blockIdx.x;
    const int lane = t & 31, warp = t >> 5;
    int i = b * SCAN_B + t;
    int v = (i < N_NODES) ? g_deg[i] : 0;
    int s = v;
    #pragma unroll
    for (int off = 1; off < 32; off <<= 1) {
        int u = __shfl_up_sync(0xffffffffu, s, off);
        if (lane >= off) s += u;
    }
    __shared__ int wsum[32];
    if (lane == 31) wsum[warp] = s;
    __syncthreads();
    if (warp == 0) {
        int ws = wsum[lane];
        #pragma unroll
        for (int off = 1; off < 32; off <<= 1) {
            int u = __shfl_up_sync(0xffffffffu, ws, off);
            if (lane >= off) ws += u;
        }
        wsum[lane] = ws;
    }
    __syncthreads();
    int add = (warp > 0) ? wsum[warp - 1] : 0;
    s += add;
    if (i < N_NODES) g_off[i] = s - v;
    if (t == SCAN_B - 1) g_bsum[b] = s;
}

__global__ void scan2_kernel() {
    const int t = threadIdx.x;           // 64 threads
    __shared__ int sh[64];
    int v = (t < SCAN_G) ? g_bsum[t] : 0;
    sh[t] = v;
    __syncthreads();
    #pragma unroll
    for (int off = 1; off < 64; off <<= 1) {
        int u = (t >= off) ? sh[t - off] : 0;
        __syncthreads();
        sh[t] += u;
        __syncthreads();
    }
    if (t < SCAN_G) g_bpre[t] = sh[t] - v;
    if (t == 63) g_off[N_NODES] = sh[63];
}

__global__ __launch_bounds__(SCAN_B) void scan3_kernel() {
    int i = blockIdx.x * SCAN_B + threadIdx.x;
    if (i >= N_NODES) return;
    int o = g_off[i] + g_bpre[blockIdx.x];
    g_off[i] = o;
    g_csr_src[o] = i;
    g_cur[i] = o + 1;
}

__global__ void scatter_kernel(const int* __restrict__ ei) {
    int e = blockIdx.x * blockDim.x + threadIdx.x;
    if (e >= N_EDGES) return;
    int s = ei[e];
    int d = ei[N_EDGES + e];
    int pos = atomicAdd(&g_cur[d], 1);
    g_csr_src[pos] = s;
}

// ---------------- layer1 GEMM (f32x2) + attention dots, fp16 store ----------------
__global__ __launch_bounds__(128) void gemm1_kernel(
    const float* __restrict__ x, const float* __restrict__ W,
    const float* __restrict__ attS, const float* __restrict__ attD)
{
    __shared__ float2 xs2[8][F0];
    const int t = threadIdx.x;
    const int quad = t & 31, slot = t >> 5;
    const int base = blockIdx.x * 8;

    #pragma unroll
    for (int r = 0; r < 8; r++) {
        float v = x[(long)(base + r) * F0 + t];
        xs2[r][t] = make_float2(v, v);
    }
    __syncthreads();

    const int r0 = slot * 2, r1 = slot * 2 + 1;
    ull a00 = 0, a01 = 0, a10 = 0, a11 = 0;
    const float* Wp = W + quad * 4;
    #pragma unroll 4
    for (int k = 0; k < F0; k++) {
        ulonglong2 w = *(const ulonglong2*)(Wp + (long)k * F1);
        ull xa = *(const ull*)&xs2[r0][k];
        ull xb = *(const ull*)&xs2[r1][k];
        ffma2(a00, w.x, xa); ffma2(a01, w.y, xa);
        ffma2(a10, w.x, xb); ffma2(a11, w.y, xb);
    }

    float4 aS = *(const float4*)&attS[quad * 4];
    float4 aD = *(const float4*)&attD[quad * 4];
    const int head = quad >> 3;

    ull pa[2] = {a00, a10}, pb[2] = {a01, a11};
    #pragma unroll
    for (int r = 0; r < 2; r++) {
        int n = base + slot * 2 + r;
        float v0, v1, v2, v3;
        unpack2(pa[r], v0, v1);
        unpack2(pb[r], v2, v3);
        __half2 h01 = __floats2half2_rn(v0, v1);
        __half2 h23 = __floats2half2_rn(v2, v3);
        uint2 pk;
        pk.x = *(unsigned*)&h01;
        pk.y = *(unsigned*)&h23;
        *(uint2*)&g_h1h[(long)n * F1 + quad * 4] = pk;
        float ps = v0 * aS.x + v1 * aS.y + v2 * aS.z + v3 * aS.w;
        float pd = v0 * aD.x + v1 * aD.y + v2 * aD.z + v3 * aD.w;
        #pragma unroll
        for (int off = 4; off > 0; off >>= 1) {
            ps += __shfl_down_sync(0xffffffffu, ps, off, 8);
            pd += __shfl_down_sync(0xffffffffu, pd, off, 8);
        }
        if ((quad & 7) == 0) {
            g_as1[n * H1 + head] = ps;
            g_ad1[n * H1 + head] = pd;
        }
    }
}

// ---------------- layer1 fused aggregate, unroll-4 software pipeline ----------------
__global__ __launch_bounds__(256) void agg1_kernel() {
    int warp = (blockIdx.x * 256 + threadIdx.x) >> 5;
    int lane = threadIdx.x & 31;
    if (warp >= N_NODES) return;
    const int n = warp;
    const int beg = g_off[n], end = g_off[n + 1];
    const int h = lane >> 3;

    const float adh = g_ad1[n * H1 + h];
    float4 acc = make_float4(0.f, 0.f, 0.f, 0.f);
    float z = 0.f;

    int p = beg;
    for (; p + 4 <= end; p += 4) {
        // batch index loads (consecutive -> one wavefront)
        int s0 = g_csr_src[p];
        int s1 = g_csr_src[p + 1];
        int s2 = g_csr_src[p + 2];
        int s3 = g_csr_src[p + 3];
        // independent gathers: 4 logits + 4 feature rows in flight
        float a0 = g_as1[s0 * H1 + h];
        float a1 = g_as1[s1 * H1 + h];
        float a2 = g_as1[s2 * H1 + h];
        float a3 = g_as1[s3 * H1 + h];
        uint2 v0 = *(const uint2*)&g_h1h[(long)s0 * F1 + lane * 4];
        uint2 v1 = *(const uint2*)&g_h1h[(long)s1 * F1 + lane * 4];
        uint2 v2 = *(const uint2*)&g_h1h[(long)s2 * F1 + lane * 4];
        uint2 v3 = *(const uint2*)&g_h1h[(long)s3 * F1 + lane * 4];

        float e0 = __expf(lrelu(a0 + adh));
        float e1 = __expf(lrelu(a1 + adh));
        float e2 = __expf(lrelu(a2 + adh));
        float e3 = __expf(lrelu(a3 + adh));
        z += (e0 + e1) + (e2 + e3);

        float2 f;
        f = __half22float2(*(__half2*)&v0.x); acc.x = fmaf(e0, f.x, acc.x); acc.y = fmaf(e0, f.y, acc.y);
        f = __half22float2(*(__half2*)&v0.y); acc.z = fmaf(e0, f.x, acc.z); acc.w = fmaf(e0, f.y, acc.w);
        f = __half22float2(*(__half2*)&v1.x); acc.x = fmaf(e1, f.x, acc.x); acc.y = fmaf(e1, f.y, acc.y);
        f = __half22float2(*(__half2*)&v1.y); acc.z = fmaf(e1, f.x, acc.z); acc.w = fmaf(e1, f.y, acc.w);
        f = __half22float2(*(__half2*)&v2.x); acc.x = fmaf(e2, f.x, acc.x); acc.y = fmaf(e2, f.y, acc.y);
        f = __half22float2(*(__half2*)&v2.y); acc.z = fmaf(e2, f.x, acc.z); acc.w = fmaf(e2, f.y, acc.w);
        f = __half22float2(*(__half2*)&v3.x); acc.x = fmaf(e3, f.x, acc.x); acc.y = fmaf(e3, f.y, acc.y);
        f = __half22float2(*(__half2*)&v3.y); acc.z = fmaf(e3, f.x, acc.z); acc.w = fmaf(e3, f.y, acc.w);
    }
    for (; p < end; p++) {
        int s = g_csr_src[p];
        float a = g_as1[s * H1 + h];
        uint2 v = *(const uint2*)&g_h1h[(long)s * F1 + lane * 4];
        float e = __expf(lrelu(a + adh));
        z += e;
        float2 f01 = __half22float2(*(__half2*)&v.x);
        float2 f23 = __half22float2(*(__half2*)&v.y);
        acc.x = fmaf(e, f01.x, acc.x);
        acc.y = fmaf(e, f01.y, acc.y);
        acc.z = fmaf(e, f23.x, acc.z);
        acc.w = fmaf(e, f23.y, acc.w);
    }

    float inv = 1.f / (z + EPS_Z);
    float4 o;
    o.x = acc.x * inv; o.y = acc.y * inv; o.z = acc.z * inv; o.w = acc.w * inv;
    *(float4*)&g_agg1[(long)n * F1 + lane * 4] = o;
}

// ---------------- layer2 GEMM (f32x2), fp16 store ----------------
__global__ __launch_bounds__(128) void gemm2_kernel(
    const float* __restrict__ b1, const float* __restrict__ W,
    const float* __restrict__ attS, const float* __restrict__ attD)
{
    __shared__ float2 xs2[8][F1];
    const int t = threadIdx.x;
    const int quad = t & 15, slot = t >> 4;
    const int base = blockIdx.x * 8;

    #pragma unroll
    for (int r = 0; r < 8; r++) {
        float v = fmaxf(g_agg1[(long)(base + r) * F1 + t] + b1[t], 0.f);
        xs2[r][t] = make_float2(v, v);
    }
    __syncthreads();

    const int n = base + slot;
    ull a0 = 0, a1 = 0;
    const float* Wp = W + quad * 4;
    #pragma unroll 4
    for (int k = 0; k < F1; k++) {
        ulonglong2 w = *(const ulonglong2*)(Wp + (long)k * F2);
        ull xv = *(const ull*)&xs2[slot][k];
        ffma2(a0, w.x, xv); ffma2(a1, w.y, xv);
    }

    float4 aS = *(const float4*)&attS[quad * 4];
    float4 aD = *(const float4*)&attD[quad * 4];
    float v0, v1, v2, v3;
    unpack2(a0, v0, v1);
    unpack2(a1, v2, v3);
    __half2 h01 = __floats2half2_rn(v0, v1);
    __half2 h23 = __floats2half2_rn(v2, v3);
    uint2 pk;
    pk.x = *(unsigned*)&h01;
    pk.y = *(unsigned*)&h23;
    *(uint2*)&g_h2h[(long)n * F2 + quad * 4] = pk;
    float ps = v0 * aS.x + v1 * aS.y + v2 * aS.z + v3 * aS.w;
    float pd = v0 * aD.x + v1 * aD.y + v2 * aD.z + v3 * aD.w;
    #pragma unroll
    for (int off = 8; off > 0; off >>= 1) {
        ps += __shfl_down_sync(0xffffffffu, ps, off, 16);
        pd += __shfl_down_sync(0xffffffffu, pd, off, 16);
    }
    if (quad == 0) {
        g_as2[n] = ps;
        g_ad2[n] = pd;
    }
}

// ---------------- layer2 fused aggregate, unroll-4 pipeline ----------------
__global__ __launch_bounds__(256) void agg2_kernel(float* __restrict__ out,
                                                   const float* __restrict__ b2) {
    int warp = (blockIdx.x * 256 + threadIdx.x) >> 5;
    int lane = threadIdx.x & 31;
    if (warp >= N_NODES) return;
    const int n = warp;
    const int beg = g_off[n], end = g_off[n + 1];

    const float ad = g_ad2[n];
    float2 acc = make_float2(0.f, 0.f);
    float z = 0.f;

    int p = beg;
    for (; p + 4 <= end; p += 4) {
        int s0 = g_csr_src[p];
        int s1 = g_csr_src[p + 1];
        int s2 = g_csr_src[p + 2];
        int s3 = g_csr_src[p + 3];
        float a0 = g_as2[s0];
        float a1 = g_as2[s1];
        float a2 = g_as2[s2];
        float a3 = g_as2[s3];
        unsigned w0 = *(const unsigned*)&g_h2h[(long)s0 * F2 + lane * 2];
        unsigned w1 = *(const unsigned*)&g_h2h[(long)s1 * F2 + lane * 2];
        unsigned w2 = *(const unsigned*)&g_h2h[(long)s2 * F2 + lane * 2];
        unsigned w3 = *(const unsigned*)&g_h2h[(long)s3 * F2 + lane * 2];

        float e0 = __expf(lrelu(a0 + ad));
        float e1 = __expf(lrelu(a1 + ad));
        float e2 = __expf(lrelu(a2 + ad));
        float e3 = __expf(lrelu(a3 + ad));
        z += (e0 + e1) + (e2 + e3);

        float2 f;
        f = __half22float2(*(__half2*)&w0); acc.x = fmaf(e0, f.x, acc.x); acc.y = fmaf(e0, f.y, acc.y);
        f = __half22float2(*(__half2*)&w1); acc.x = fmaf(e1, f.x, acc.x); acc.y = fmaf(e1, f.y, acc.y);
        f = __half22float2(*(__half2*)&w2); acc.x = fmaf(e2, f.x, acc.x); acc.y = fmaf(e2, f.y, acc.y);
        f = __half22float2(*(__half2*)&w3); acc.x = fmaf(e3, f.x, acc.x); acc.y = fmaf(e3, f.y, acc.y);
    }
    for (; p < end; p++) {
        int s = g_csr_src[p];
        float a = g_as2[s];
        unsigned w = *(const unsigned*)&g_h2h[(long)s * F2 + lane * 2];
        float e = __expf(lrelu(a + ad));
        z += e;
        float2 f = __half22float2(*(__half2*)&w);
        acc.x = fmaf(e, f.x, acc.x);
        acc.y = fmaf(e, f.y, acc.y);
    }

    float inv = 1.f / (z + EPS_Z);
    float2 bb = *(const float2*)&b2[lane * 2];
    float2 o;
    o.x = fmaxf(acc.x * inv + bb.x, 0.f);
    o.y = fmaxf(acc.y * inv + bb.y, 0.f);
    *(float2*)&out[(long)n * F2 + lane * 2] = o;
}

// ---------------- host ----------------
extern "C" void kernel_launch(void* const* d_in, const int* in_sizes, int n_in,
                              void* d_out, int out_size)
{
    const float* x     = (const float*)d_in[0];
    const int*   ei    = (const int*)  d_in[1];
    const float* W1    = (const float*)d_in[2];
    const float* attS1 = (const float*)d_in[3];
    const float* attD1 = (const float*)d_in[4];
    const float* b1    = (const float*)d_in[5];
    const float* W2    = (const float*)d_in[6];
    const float* attS2 = (const float*)d_in[7];
    const float* attD2 = (const float*)d_in[8];
    const float* b2    = (const float*)d_in[9];
    float* out = (float*)d_out;

    static cudaStream_t s2 = nullptr;
    static cudaEvent_t evFork = nullptr, evJoin = nullptr;
    if (!s2) {
        cudaStreamCreateWithFlags(&s2, cudaStreamNonBlocking);
        cudaEventCreateWithFlags(&evFork, cudaEventDisableTiming);
        cudaEventCreateWithFlags(&evJoin, cudaEventDisableTiming);
    }

    const int TB = 256;

    // fork: gemm1 overlaps the CSR build
    cudaEventRecord(evFork, 0);
    cudaStreamWaitEvent(s2, evFork, 0);
    gemm1_kernel<<<N_NODES / 8, 128, 0, s2>>>(x, W1, attS1, attD1);
    cudaEventRecord(evJoin, s2);

    // CSR build (main stream)
    zero_cnt_kernel<<<(N_NODES + TB - 1) / TB, TB>>>();
    hist_kernel<<<(N_EDGES + TB - 1) / TB, TB>>>(ei);
    scan1_kernel<<<SCAN_G, SCAN_B>>>();
    scan2_kernel<<<1, 64>>>();
    scan3_kernel<<<SCAN_G, SCAN_B>>>();
    scatter_kernel<<<(N_EDGES + TB - 1) / TB, TB>>>(ei);

    cudaStreamWaitEvent(0, evJoin, 0);
    agg1_kernel<<<(N_NODES * 32 + TB - 1) / TB, TB>>>();

    gemm2_kernel<<<N_NODES / 8, 128>>>(b1, W2, attS2, attD2);
    agg2_kernel<<<(N_NODES * 32 + TB - 1) / TB, TB>>>(out, b2);
}